// round 10
// baseline (speedup 1.0000x reference)
#include <cuda_runtime.h>
#include <math.h>
#include <stdint.h>

// Fixed problem sizes (guarded at runtime by in_sizes)
#define EMAX 120000
#define NMAX 5000

// ---------------- scratch (device globals; no allocation allowed) ------------
// Activations stored as bf16 hi/lo pairs packed 2-per-uint32 along feature dim.
__device__ uint32_t g_pcat_hi[(size_t)EMAX * 256], g_pcat_lo[(size_t)EMAX * 256]; // 512-wide
__device__ uint32_t g_pe1_hi [(size_t)EMAX * 128], g_pe1_lo [(size_t)EMAX * 128]; // 256-wide
__device__ uint32_t g_pe2_hi [(size_t)EMAX * 128], g_pe2_lo [(size_t)EMAX * 128];
__device__ uint32_t g_pat_hi [(size_t)EMAX * 128], g_pat_lo [(size_t)EMAX * 128];
__device__ uint32_t g_ph_hi  [(size_t)NMAX * 128], g_ph_lo  [(size_t)NMAX * 128];
__device__ uint32_t g_pnt_hi [(size_t)NMAX * 128], g_pnt_lo [(size_t)NMAX * 128];
__device__ uint32_t g_pag_hi [(size_t)NMAX * 128], g_pag_lo [(size_t)NMAX * 128];
__device__ float    g_dlen[EMAX];
__device__ uint32_t g_wsplit[1600000];   // pre-split weights (bf16 hi/lo, n-major)

// ---------------- activations ------------------------------------------------
__device__ __forceinline__ float silu_f(float x) { return x / (1.f + expf(-x)); }
__device__ __forceinline__ float ssp_f(float x) {
    float sp = (x > 15.f) ? x : log1pf(expf(x));
    return sp - 0.69314718056f;
}
template<int ACT>
__device__ __forceinline__ float act_apply(float x) {
    if (ACT == 1) return silu_f(x);
    if (ACT == 2) return ssp_f(x);
    return x;
}

// ---------------- bf16 pair pack / split / reconstruct -----------------------
__device__ __forceinline__ uint32_t pack2(float f0, float f1) {
    uint32_t r;
    asm("cvt.rn.bf16x2.f32 %0, %1, %2;" : "=r"(r) : "f"(f1), "f"(f0));
    return r;
}
__device__ __forceinline__ void split2(float f0, float f1, uint32_t& hi, uint32_t& lo) {
    hi = pack2(f0, f1);
    float h0 = __uint_as_float(hi << 16);
    float h1 = __uint_as_float(hi & 0xffff0000u);
    lo = pack2(f0 - h0, f1 - h1);
}
__device__ __forceinline__ void recon2(uint32_t hi, uint32_t lo, float& f0, float& f1) {
    f0 = __uint_as_float(hi << 16)        + __uint_as_float(lo << 16);
    f1 = __uint_as_float(hi & 0xffff0000u) + __uint_as_float(lo & 0xffff0000u);
}

// ---------------- mma / ldmatrix ----------------------------------------------
__device__ __forceinline__ void mma16(float* d, const uint32_t* a, const uint32_t* b) {
    asm volatile(
        "mma.sync.aligned.m16n8k16.row.col.f32.bf16.bf16.f32 "
        "{%0,%1,%2,%3}, {%4,%5,%6,%7}, {%8,%9}, {%0,%1,%2,%3};"
        : "+f"(d[0]), "+f"(d[1]), "+f"(d[2]), "+f"(d[3])
        : "r"(a[0]), "r"(a[1]), "r"(a[2]), "r"(a[3]), "r"(b[0]), "r"(b[1]));
}
__device__ __forceinline__ void ldsm4(uint32_t& r0, uint32_t& r1, uint32_t& r2, uint32_t& r3,
                                      uint32_t saddr) {
    asm volatile("ldmatrix.sync.aligned.m8n8.x4.shared.b16 {%0,%1,%2,%3}, [%4];"
                 : "=r"(r0), "=r"(r1), "=r"(r2), "=r"(r3) : "r"(saddr));
}

// ---------------- bf16x3 tensor-core GEMM with ldmatrix -----------------------
// C = act(A @ B + bias) via Ahi@Bhi + Alo@Bhi + Ahi@Blo (fp32 acc).
// A packed [M][K/2] u32 (bf16x2 along K, k-major).
// B (weights) packed [N][K/2] u32 (n-major!) so B frags load with plain ldmatrix.
// Output pair-packed [M][N/2]. BM=BN=128, BK=32 (16 kpairs), 128 threads.
template<int ACT, bool ADD>
__global__ __launch_bounds__(128, 2) void bgemm(
    const uint32_t* __restrict__ Ahi, const uint32_t* __restrict__ Alo,
    const uint32_t* __restrict__ Bhi, const uint32_t* __restrict__ Blo,
    const float* __restrict__ bias,
    uint32_t* __restrict__ Chi, uint32_t* __restrict__ Clo,
    int M, int K, int N)
{
    __shared__ uint32_t As[2][128][20];   // [hi/lo][row][kpair], pad 20 (LDSM bank-free)
    __shared__ uint32_t Bs[2][128][20];   // [hi/lo][ncol][kpair], pad 20

    const int tid  = threadIdx.x;
    const int wid  = tid >> 5;
    const int lane = tid & 31;
    const int tig  = lane & 3;
    const int gid  = lane >> 2;
    const int wm   = wid & 1;
    const int wn   = wid >> 1;
    const int r0   = blockIdx.y * 128;
    const int c0   = blockIdx.x * 128;
    const int Kp   = K >> 1;             // packed K width
    (void)gid;

    // per-lane ldmatrix row/col selectors
    const int a_row_in = ((lane >> 3) & 1) * 8 + (lane & 7);  // tiles: row +(t&1)*8
    const int a_kp_sel = (lane >> 4) * 4;                     //        kp  +(t>>1)*4
    const int b_col_in = (lane >> 4) * 8 + (lane & 7);        // tiles: col +(t>>1)*8
    const int b_kp_sel = ((lane >> 3) & 1) * 4;               //        kp  +(t&1)*4

    const uint32_t sA = (uint32_t)__cvta_generic_to_shared(&As[0][0][0]);
    const uint32_t sB = (uint32_t)__cvta_generic_to_shared(&Bs[0][0][0]);
    // base addresses (h=0); h=1 adds 128*20*4 = 10240 bytes
    const uint32_t aBase = sA + (uint32_t)(((wm * 64 + a_row_in) * 20 + a_kp_sel) * 4);
    const uint32_t bBase = sB + (uint32_t)(((wn * 64 + b_col_in) * 20 + b_kp_sel) * 4);

    float acc[4][8][4];
#pragma unroll
    for (int mf = 0; mf < 4; mf++)
#pragma unroll
        for (int nf = 0; nf < 8; nf++)
#pragma unroll
            for (int i = 0; i < 4; i++) acc[mf][nf][i] = 0.f;

    for (int kp0 = 0; kp0 < Kp; kp0 += 16) {
        // ---- A tiles: 128 rows x 16 kpairs, hi & lo (k-major source)
        {
            int row  = (tid >> 2);
            int col4 = (tid & 3) * 4;
#pragma unroll
            for (int p = 0; p < 4; p++) {
                int r = row + p * 32;
                int grow = r0 + r;
                uint4 vh = make_uint4(0u, 0u, 0u, 0u), vl = vh;
                if (grow < M) {
                    size_t g = (size_t)grow * Kp + kp0 + col4;
                    vh = *reinterpret_cast<const uint4*>(&Ahi[g]);
                    vl = *reinterpret_cast<const uint4*>(&Alo[g]);
                }
                *reinterpret_cast<uint4*>(&As[0][r][col4]) = vh;
                *reinterpret_cast<uint4*>(&As[1][r][col4]) = vl;
            }
        }
        // ---- B tiles: 128 ncols x 16 kpairs, hi & lo (n-major source)
        {
            int colb = (tid >> 2);
            int u4   = (tid & 3) * 4;
#pragma unroll
            for (int p = 0; p < 4; p++) {
                int col = colb + p * 32;
                size_t g = (size_t)(c0 + col) * Kp + kp0 + u4;
                uint4 vh = *reinterpret_cast<const uint4*>(&Bhi[g]);
                uint4 vl = *reinterpret_cast<const uint4*>(&Blo[g]);
                *reinterpret_cast<uint4*>(&Bs[0][col][u4]) = vh;
                *reinterpret_cast<uint4*>(&Bs[1][col][u4]) = vl;
            }
        }
        __syncthreads();

#pragma unroll
        for (int k16 = 0; k16 < 2; k16++) {
            const uint32_t kof = (uint32_t)(k16 * 8 * 4);   // bp*4 bytes
            uint32_t ah[4][4], al[4][4];
#pragma unroll
            for (int mf = 0; mf < 4; mf++) {
                uint32_t adr = aBase + kof + (uint32_t)(mf * 16 * 20 * 4);
                ldsm4(ah[mf][0], ah[mf][1], ah[mf][2], ah[mf][3], adr);
                ldsm4(al[mf][0], al[mf][1], al[mf][2], al[mf][3], adr + 10240u);
            }
#pragma unroll
            for (int nfp = 0; nfp < 4; nfp++) {
                uint32_t bdr = bBase + kof + (uint32_t)(nfp * 16 * 20 * 4);
                uint32_t bh[4], bl[4];
                ldsm4(bh[0], bh[1], bh[2], bh[3], bdr);
                ldsm4(bl[0], bl[1], bl[2], bl[3], bdr + 10240u);
#pragma unroll
                for (int e = 0; e < 2; e++) {
                    const int nf = nfp * 2 + e;
#pragma unroll
                    for (int mf = 0; mf < 4; mf++) mma16(acc[mf][nf], ah[mf], &bh[e * 2]);
#pragma unroll
                    for (int mf = 0; mf < 4; mf++) mma16(acc[mf][nf], al[mf], &bh[e * 2]);
#pragma unroll
                    for (int mf = 0; mf < 4; mf++) mma16(acc[mf][nf], ah[mf], &bl[e * 2]);
                }
            }
        }
        __syncthreads();
    }

    // ---- epilogue: bias + act (+residual), split to bf16 pair, store --------
    const int Np = N >> 1;
#pragma unroll
    for (int mf = 0; mf < 4; mf++) {
#pragma unroll
        for (int nf = 0; nf < 8; nf++) {
            int gc = c0 + wn * 64 + nf * 8 + 2 * tig;   // even global col
            int pc = gc >> 1;                            // pair index
            float bz0 = bias ? bias[gc]     : 0.f;
            float bz1 = bias ? bias[gc + 1] : 0.f;
#pragma unroll
            for (int half = 0; half < 2; half++) {
                int r = r0 + wm * 64 + mf * 16 + (lane >> 2) + half * 8;
                if (r >= M) continue;
                float v0 = act_apply<ACT>(acc[mf][nf][half * 2 + 0] + bz0);
                float v1 = act_apply<ACT>(acc[mf][nf][half * 2 + 1] + bz1);
                size_t idx = (size_t)r * Np + pc;
                if (ADD) {
                    float o0, o1;
                    recon2(Chi[idx], Clo[idx], o0, o1);
                    v0 += o0; v1 += o1;
                }
                uint32_t h, l;
                split2(v0, v1, h, l);
                Chi[idx] = h; Clo[idx] = l;
            }
        }
    }
}

// ---------------- weight pre-split: W[K,N] fp32 -> hi/lo [N][K/2] n-major -----
__global__ void k_splitW(const float* __restrict__ W, uint32_t* __restrict__ hi,
                         uint32_t* __restrict__ lo, int P, int Ncols)
{
    int idx = blockIdx.x * 256 + threadIdx.x;
    if (idx >= P * Ncols) return;
    int n = idx / P, p = idx - n * P;         // output layout: [n][p]
    float f0 = W[(size_t)(2 * p)     * Ncols + n];
    float f1 = W[(size_t)(2 * p + 1) * Ncols + n];
    uint32_t h, l;
    split2(f0, f1, h, l);
    hi[idx] = h; lo[idx] = l;
}

// ---------------- node embedding: z = cat(emb[at]+fr, fp-fr), packed ---------
__global__ void k_node_embed(const float* __restrict__ r_feat, const float* __restrict__ p_feat,
                             const float* __restrict__ emb, const float* __restrict__ Wf,
                             const int* __restrict__ at,
                             uint32_t* __restrict__ hhi, uint32_t* __restrict__ hlo)
{
    int n = blockIdx.x, c = threadIdx.x;        // 64 threads, pair of cols (2c,2c+1)
    __shared__ float rs[27], ps[27];
    if (c < 27) { rs[c] = r_feat[n * 27 + c]; ps[c] = p_feat[n * 27 + c]; }
    __syncthreads();
    float fr0 = 0.f, fr1 = 0.f, fp0 = 0.f, fp1 = 0.f;
#pragma unroll
    for (int k = 0; k < 27; k++) {
        float w0 = Wf[k * 128 + 2 * c], w1 = Wf[k * 128 + 2 * c + 1];
        fr0 = fmaf(rs[k], w0, fr0); fr1 = fmaf(rs[k], w1, fr1);
        fp0 = fmaf(ps[k], w0, fp0); fp1 = fmaf(ps[k], w1, fp1);
    }
    int t = at[n];
    float e0 = emb[t * 128 + 2 * c], e1 = emb[t * 128 + 2 * c + 1];
    uint32_t h, l;
    split2(e0 + fr0, e1 + fr1, h, l);
    hhi[(size_t)n * 128 + c] = h;  hlo[(size_t)n * 128 + c] = l;
    split2(fp0 - fr0, fp1 - fr1, h, l);
    hhi[(size_t)n * 128 + 64 + c] = h;  hlo[(size_t)n * 128 + 64 + c] = l;
}

// ---------------- edge length + silu(d*W1+b1), packed ------------------------
__global__ void k_edge_d_h1(const float* __restrict__ pos, const int* __restrict__ ei,
                            const float* __restrict__ W1, const float* __restrict__ b1,
                            float* __restrict__ dlen,
                            uint32_t* __restrict__ ohi, uint32_t* __restrict__ olo, int E)
{
    int e = blockIdx.x, c = threadIdx.x;        // 128 threads, cols (2c,2c+1)
    int s = ei[e], t = ei[E + e];
    float dx = pos[t * 3 + 0] - pos[s * 3 + 0];
    float dy = pos[t * 3 + 1] - pos[s * 3 + 1];
    float dz = pos[t * 3 + 2] - pos[s * 3 + 2];
    float d = sqrtf(dx * dx + dy * dy + dz * dz);
    if (c == 0) dlen[e] = d;
    float v0 = silu_f(fmaf(d, W1[2 * c], b1[2 * c]));
    float v1 = silu_f(fmaf(d, W1[2 * c + 1], b1[2 * c + 1]));
    uint32_t h, l;
    split2(v0, v1, h, l);
    ohi[(size_t)e * 128 + c] = h;  olo[(size_t)e * 128 + c] = l;
}

// ---------------- bond gating + concatenation, packed ------------------------
__global__ void k_bondgate(const uint32_t* __restrict__ mhi, const uint32_t* __restrict__ mlo,
                           const float* __restrict__ bemb,
                           const int* __restrict__ tr, const int* __restrict__ tp,
                           uint32_t* __restrict__ ohi, uint32_t* __restrict__ olo)
{
    int e = blockIdx.x, c = threadIdx.x;        // 128 threads
    float v0, v1;
    recon2(mhi[(size_t)e * 128 + c], mlo[(size_t)e * 128 + c], v0, v1);
    int ir = tr[e] * 256 + 2 * c, ip = tp[e] * 256 + 2 * c;
    uint32_t h, l;
    split2(v0 * bemb[ir], v1 * bemb[ir + 1], h, l);
    ohi[(size_t)e * 256 + c] = h;        olo[(size_t)e * 256 + c] = l;
    split2(v0 * bemb[ip], v1 * bemb[ip + 1], h, l);
    ohi[(size_t)e * 256 + 128 + c] = h;  olo[(size_t)e * 256 + 128 + c] = l;
}

// ---------------- deterministic gather aggregation (segment_sum), packed -----
// e = g*600 + i*24 + (j - (j > i)),  src = g*25 + i, dst = g*25 + j
__global__ void k_aggregate(const uint32_t* __restrict__ nhi, const uint32_t* __restrict__ nlo,
                            const uint32_t* __restrict__ whi, const uint32_t* __restrict__ wlo,
                            uint32_t* __restrict__ ahi, uint32_t* __restrict__ alo)
{
    int n = blockIdx.x, c = threadIdx.x;        // 128 threads = pairs
    int g = n / 25, j = n % 25;
    int base_e = g * 600, base_n = g * 25;
    float a0 = 0.f, a1 = 0.f;
#pragma unroll
    for (int i = 0; i < 25; i++) {
        if (i == j) continue;
        int e = base_e + i * 24 + (j - (int)(j > i));
        float x0, x1, w0, w1;
        recon2(nhi[(size_t)(base_n + i) * 128 + c], nlo[(size_t)(base_n + i) * 128 + c], x0, x1);
        recon2(whi[(size_t)e * 128 + c],            wlo[(size_t)e * 128 + c],            w0, w1);
        a0 = fmaf(x0, w0, a0);
        a1 = fmaf(x1, w1, a1);
    }
    uint32_t h, l;
    split2(a0, a1, h, l);
    ahi[(size_t)n * 128 + c] = h;  alo[(size_t)n * 128 + c] = l;
}

// ---------------- pair assembly, packed --------------------------------------
__global__ void k_pair(const uint32_t* __restrict__ hhi, const uint32_t* __restrict__ hlo,
                       const uint32_t* __restrict__ ehi, const uint32_t* __restrict__ elo,
                       const int* __restrict__ ei,
                       uint32_t* __restrict__ ohi, uint32_t* __restrict__ olo, int E)
{
    int e = blockIdx.x, c = threadIdx.x;        // 256 threads = 256 pairs
    if (c < 128) {
        int s = ei[e], t = ei[E + e];
        float s0, s1, t0, t1;
        recon2(hhi[(size_t)s * 128 + c], hlo[(size_t)s * 128 + c], s0, s1);
        recon2(hhi[(size_t)t * 128 + c], hlo[(size_t)t * 128 + c], t0, t1);
        uint32_t h, l;
        split2(s0 * t0, s1 * t1, h, l);
        ohi[(size_t)e * 256 + c] = h;  olo[(size_t)e * 256 + c] = l;
    } else {
        int c2 = c - 128;
        ohi[(size_t)e * 256 + c] = ehi[(size_t)e * 128 + c2];
        olo[(size_t)e * 256 + c] = elo[(size_t)e * 128 + c2];
    }
}

// ---------------- final projection [E,128] @ [128,1] + b ---------------------
__global__ void k_final(const uint32_t* __restrict__ xhi, const uint32_t* __restrict__ xlo,
                        const float* __restrict__ W3, const float* __restrict__ b3,
                        float* __restrict__ out, int E)
{
    int e = blockIdx.x * 8 + (threadIdx.x >> 5);
    int lane = threadIdx.x & 31;
    if (e >= E) return;
    float acc = 0.f;
#pragma unroll
    for (int q = 0; q < 2; q++) {
        int p = q * 32 + lane;              // pair index 0..63
        float v0, v1;
        recon2(xhi[(size_t)e * 64 + p], xlo[(size_t)e * 64 + p], v0, v1);
        acc = fmaf(v0, W3[2 * p], acc);
        acc = fmaf(v1, W3[2 * p + 1], acc);
    }
#pragma unroll
    for (int o = 16; o; o >>= 1) acc += __shfl_xor_sync(0xffffffffu, acc, o);
    if (lane == 0) out[e] = acc + b3[0];
}

// ---------------- extra outputs (edge_index as float, d) ---------------------
__global__ void k_extras(const int* __restrict__ ei, const float* __restrict__ dlen,
                         float* __restrict__ out, int E)
{
    int k = blockIdx.x * 256 + threadIdx.x;
    if (k < 2 * E) out[E + k] = (float)ei[k];
    if (k < E)     out[3 * E + k] = dlen[k];
}

// ---------------- GEMM dispatch ----------------------------------------------
static void gemm(const uint32_t* Ahi, const uint32_t* Alo,
                 const uint32_t* Bhi, const uint32_t* Blo,
                 const float* bias, uint32_t* Chi, uint32_t* Clo,
                 int M, int K, int N, int act, bool add)
{
    dim3 grid(N / 128, (M + 127) / 128);
    if (add) {
        bgemm<2, true><<<grid, 128>>>(Ahi, Alo, Bhi, Blo, bias, Chi, Clo, M, K, N);
        return;
    }
    switch (act) {
        case 0: bgemm<0, false><<<grid, 128>>>(Ahi, Alo, Bhi, Blo, bias, Chi, Clo, M, K, N); break;
        case 1: bgemm<1, false><<<grid, 128>>>(Ahi, Alo, Bhi, Blo, bias, Chi, Clo, M, K, N); break;
        case 2: bgemm<2, false><<<grid, 128>>>(Ahi, Alo, Bhi, Blo, bias, Chi, Clo, M, K, N); break;
    }
}

extern "C" void kernel_launch(void* const* d_in, const int* in_sizes, int n_in,
                              void* d_out, int out_size)
{
    const float* pos      = (const float*)d_in[0];
    const float* r_feat   = (const float*)d_in[1];
    const float* p_feat   = (const float*)d_in[2];
    const float* emb_tab  = (const float*)d_in[3];
    const float* feat_W   = (const float*)d_in[4];
    const float* bond_emb = (const float*)d_in[5];
    const float* ee_W1    = (const float*)d_in[6];
    const float* ee_b1    = (const float*)d_in[7];
    const float* ee_W2    = (const float*)d_in[8];
    const float* ee_b2    = (const float*)d_in[9];
    const float* ec_W1    = (const float*)d_in[10];
    const float* ec_b1    = (const float*)d_in[11];
    const float* ec_W2    = (const float*)d_in[12];
    const float* ec_b2    = (const float*)d_in[13];
    const float* fW1      = (const float*)d_in[14];
    const float* fb1      = (const float*)d_in[15];
    const float* fW2      = (const float*)d_in[16];
    const float* fb2      = (const float*)d_in[17];
    const float* lin1     = (const float*)d_in[18];
    const float* lin2     = (const float*)d_in[19];
    const float* lin2b    = (const float*)d_in[20];
    const float* g_W1     = (const float*)d_in[21];
    const float* g_b1     = (const float*)d_in[22];
    const float* g_W2     = (const float*)d_in[23];
    const float* g_b2     = (const float*)d_in[24];
    const float* g_W3     = (const float*)d_in[25];
    const float* g_b3     = (const float*)d_in[26];
    const int*   at       = (const int*)d_in[27];
    const int*   ei       = (const int*)d_in[28];
    const int*   tr       = (const int*)d_in[29];
    const int*   tp       = (const int*)d_in[30];

    const int N = in_sizes[0] / 3;     // nodes
    const int E = in_sizes[28] / 2;    // edges

    uint32_t *pcat_hi, *pcat_lo, *pe1_hi, *pe1_lo, *pe2_hi, *pe2_lo;
    uint32_t *pat_hi, *pat_lo, *ph_hi, *ph_lo, *pnt_hi, *pnt_lo, *pag_hi, *pag_lo, *wsplit;
    float *dlen;
    cudaGetSymbolAddress((void**)&pcat_hi, g_pcat_hi);
    cudaGetSymbolAddress((void**)&pcat_lo, g_pcat_lo);
    cudaGetSymbolAddress((void**)&pe1_hi,  g_pe1_hi);
    cudaGetSymbolAddress((void**)&pe1_lo,  g_pe1_lo);
    cudaGetSymbolAddress((void**)&pe2_hi,  g_pe2_hi);
    cudaGetSymbolAddress((void**)&pe2_lo,  g_pe2_lo);
    cudaGetSymbolAddress((void**)&pat_hi,  g_pat_hi);
    cudaGetSymbolAddress((void**)&pat_lo,  g_pat_lo);
    cudaGetSymbolAddress((void**)&ph_hi,   g_ph_hi);
    cudaGetSymbolAddress((void**)&ph_lo,   g_ph_lo);
    cudaGetSymbolAddress((void**)&pnt_hi,  g_pnt_hi);
    cudaGetSymbolAddress((void**)&pnt_lo,  g_pnt_lo);
    cudaGetSymbolAddress((void**)&pag_hi,  g_pag_hi);
    cudaGetSymbolAddress((void**)&pag_lo,  g_pag_lo);
    cudaGetSymbolAddress((void**)&wsplit,  g_wsplit);
    cudaGetSymbolAddress((void**)&dlen,    g_dlen);

    float* out = (float*)d_out;

    // ---- pre-split all GEMM weights into bf16 hi/lo (n-major [N][K/2]) ------
    // Index map: 0..2 = edge-embedding weights, 3..18 = conv (4 per layer),
    //            19 = g_W1, 20 = g_W2.   (21 slots.)
    size_t off = 0;
    const uint32_t* Wh[21]; const uint32_t* Wl[21];
    auto splitw = [&](int idx, const float* W, int K, int Nc) {
        int P = K / 2;
        size_t S = (size_t)P * Nc;
        uint32_t* hi = wsplit + off;
        uint32_t* lo = wsplit + off + S;
        k_splitW<<<(int)((S + 255) / 256), 256>>>(W, hi, lo, P, Nc);
        Wh[idx] = hi; Wl[idx] = lo;
        off += 2 * S;
    };
    splitw(0, ee_W2, 256, 256);
    splitw(1, ec_W1, 512, 256);
    splitw(2, ec_W2, 256, 256);
    for (int l = 0; l < 4; l++) {
        splitw(3 + l * 4 + 0, fW1  + (size_t)l * 65536, 256, 256);
        splitw(3 + l * 4 + 1, fW2  + (size_t)l * 65536, 256, 256);
        splitw(3 + l * 4 + 2, lin1 + (size_t)l * 65536, 256, 256);
        splitw(3 + l * 4 + 3, lin2 + (size_t)l * 65536, 256, 256);
    }
    splitw(19, g_W1, 512, 256);
    splitw(20, g_W2, 256, 128);

    // 1) node embedding -> ph (packed)
    k_node_embed<<<N, 64>>>(r_feat, p_feat, emb_tab, feat_W, at, ph_hi, ph_lo);

    // 2) edge length + silu(d*W1+b1) -> pe1
    k_edge_d_h1<<<E, 128>>>(pos, ei, ee_W1, ee_b1, dlen, pe1_hi, pe1_lo, E);

    // 3) mlp_d = pe1 @ ee_W2 + ee_b2 -> pe2
    gemm(pe1_hi, pe1_lo, Wh[0], Wl[0], ee_b2, pe2_hi, pe2_lo, E, 256, 256, 0, false);

    // 4) gate by bond embeddings, cat(r,p) -> pcat (512-wide)
    k_bondgate<<<E, 128>>>(pe2_hi, pe2_lo, bond_emb, tr, tp, pcat_hi, pcat_lo);

    // 5) edge_attr = silu(pcat @ ec_W1 + b1) @ ec_W2 + b2 -> pat
    gemm(pcat_hi, pcat_lo, Wh[1], Wl[1], ec_b1, pe1_hi, pe1_lo, E, 512, 256, 1, false);
    gemm(pe1_hi, pe1_lo, Wh[2], Wl[2], ec_b2, pat_hi, pat_lo, E, 256, 256, 0, false);

    // 6) 4 CFConv interaction blocks
    for (int l = 0; l < 4; l++) {
        const float* b1  = fb1  + (size_t)l * 256;
        const float* b2  = fb2  + (size_t)l * 256;
        const float* l2b = lin2b + (size_t)l * 256;
        int wi = 3 + l * 4;

        gemm(pat_hi, pat_lo, Wh[wi + 0], Wl[wi + 0], b1, pe1_hi, pe1_lo, E, 256, 256, 2, false); // ssp
        gemm(pe1_hi, pe1_lo, Wh[wi + 1], Wl[wi + 1], b2, pe2_hi, pe2_lo, E, 256, 256, 0, false); // W_e
        gemm(ph_hi, ph_lo, Wh[wi + 2], Wl[wi + 2], nullptr, pnt_hi, pnt_lo, N, 256, 256, 0, false);
        k_aggregate<<<N, 128>>>(pnt_hi, pnt_lo, pe2_hi, pe2_lo, pag_hi, pag_lo);
        gemm(pag_hi, pag_lo, Wh[wi + 3], Wl[wi + 3], l2b, ph_hi, ph_lo, N, 256, 256, 2, true);   // h += ssp
    }

    // 7) pair features -> pcat
    k_pair<<<E, 256>>>(ph_hi, ph_lo, pat_hi, pat_lo, ei, pcat_hi, pcat_lo, E);

    // 8) output head
    gemm(pcat_hi, pcat_lo, Wh[19], Wl[19], g_b1, pe1_hi, pe1_lo, E, 512, 256, 1, false);
    gemm(pe1_hi, pe1_lo, Wh[20], Wl[20], g_b2, pe2_hi, pe2_lo, E, 256, 128, 1, false);
    k_final<<<(E + 7) / 8, 256>>>(pe2_hi, pe2_lo, g_W3, g_b3, out, E);

    // 9) remaining tuple outputs (edge_index, d) if compared
    if (out_size >= 4 * E) {
        k_extras<<<(2 * E + 255) / 256, 256>>>(ei, dlen, out, E);
    }
}

// round 12
// speedup vs baseline: 1.2398x; 1.2398x over previous
#include <cuda_runtime.h>
#include <math.h>
#include <stdint.h>

// Fixed problem sizes (guarded at runtime by in_sizes)
#define EMAX 120000
#define NMAX 5000

// ---------------- scratch (device globals; no allocation allowed) ------------
__device__ uint32_t g_pcat_hi[(size_t)EMAX * 256], g_pcat_lo[(size_t)EMAX * 256]; // 512-wide
__device__ uint32_t g_pe1_hi [(size_t)EMAX * 128], g_pe1_lo [(size_t)EMAX * 128]; // 256-wide
__device__ uint32_t g_pe2_hi [(size_t)EMAX * 128], g_pe2_lo [(size_t)EMAX * 128];
__device__ uint32_t g_pat_hi [(size_t)EMAX * 128], g_pat_lo [(size_t)EMAX * 128];
__device__ uint32_t g_ph_hi  [(size_t)NMAX * 128], g_ph_lo  [(size_t)NMAX * 128];
__device__ uint32_t g_pnt_hi [(size_t)NMAX * 128], g_pnt_lo [(size_t)NMAX * 128];
__device__ uint32_t g_pag_hi [(size_t)NMAX * 128], g_pag_lo [(size_t)NMAX * 128];
__device__ float    g_dlen[EMAX];
__device__ uint32_t g_wsplit[1600000];   // pre-split weights (bf16 hi/lo, n-major)

// ---------------- activations ------------------------------------------------
__device__ __forceinline__ float silu_f(float x) { return x / (1.f + expf(-x)); }
__device__ __forceinline__ float ssp_f(float x) {
    float sp = (x > 15.f) ? x : log1pf(expf(x));
    return sp - 0.69314718056f;
}
template<int ACT>
__device__ __forceinline__ float act_apply(float x) {
    if (ACT == 1) return silu_f(x);
    if (ACT == 2) return ssp_f(x);
    return x;
}

// ---------------- bf16 pair pack / split / reconstruct -----------------------
__device__ __forceinline__ uint32_t pack2(float f0, float f1) {
    uint32_t r;
    asm("cvt.rn.bf16x2.f32 %0, %1, %2;" : "=r"(r) : "f"(f1), "f"(f0));
    return r;
}
__device__ __forceinline__ void split2(float f0, float f1, uint32_t& hi, uint32_t& lo) {
    hi = pack2(f0, f1);
    float h0 = __uint_as_float(hi << 16);
    float h1 = __uint_as_float(hi & 0xffff0000u);
    lo = pack2(f0 - h0, f1 - h1);
}
__device__ __forceinline__ void recon2(uint32_t hi, uint32_t lo, float& f0, float& f1) {
    f0 = __uint_as_float(hi << 16)        + __uint_as_float(lo << 16);
    f1 = __uint_as_float(hi & 0xffff0000u) + __uint_as_float(lo & 0xffff0000u);
}

// ---------------- mma / ldmatrix / cp.async -----------------------------------
__device__ __forceinline__ void mma16(float* d, const uint32_t* a, const uint32_t* b) {
    asm volatile(
        "mma.sync.aligned.m16n8k16.row.col.f32.bf16.bf16.f32 "
        "{%0,%1,%2,%3}, {%4,%5,%6,%7}, {%8,%9}, {%0,%1,%2,%3};"
        : "+f"(d[0]), "+f"(d[1]), "+f"(d[2]), "+f"(d[3])
        : "r"(a[0]), "r"(a[1]), "r"(a[2]), "r"(a[3]), "r"(b[0]), "r"(b[1]));
}
__device__ __forceinline__ void ldsm4(uint32_t& r0, uint32_t& r1, uint32_t& r2, uint32_t& r3,
                                      uint32_t saddr) {
    asm volatile("ldmatrix.sync.aligned.m8n8.x4.shared.b16 {%0,%1,%2,%3}, [%4];"
                 : "=r"(r0), "=r"(r1), "=r"(r2), "=r"(r3) : "r"(saddr));
}
__device__ __forceinline__ void cp16(uint32_t sdst, const void* gsrc, uint32_t sz) {
    asm volatile("cp.async.cg.shared.global [%0], [%1], 16, %2;"
                 :: "r"(sdst), "l"(gsrc), "r"(sz) : "memory");
}
__device__ __forceinline__ void cp_commit() {
    asm volatile("cp.async.commit_group;" ::: "memory");
}
__device__ __forceinline__ uint32_t smem_u32(const void* p) {
    uint32_t a;
    asm("{ .reg .u64 t; cvta.to.shared.u64 t, %1; cvt.u32.u64 %0, t; }" : "=r"(a) : "l"(p));
    return a;
}

// ---------------- bf16x3 tensor-core GEMM, cp.async double-buffered -----------
// C = act(A @ B + bias) via Ahi@Bhi + Alo@Bhi + Ahi@Blo (fp32 acc).
// A packed [M][K/2] u32 (bf16x2 k-major). B (weights) packed [Ntot][K/2] (n-major).
// BM=BN=128, tile = 16 kpairs (32 bf16). 256 threads = 8 warps (2x4), warp 64x32.
// Dyn smem: stage0 {A 20480, B 20480}, stage1 {A, B} -> 81920 bytes.
#define TILE_U32S   (128 * 20)            // one [128][20] u32 plane
#define HILO_OFF    10240u                // 128*20*4 bytes
#define A0_OFF      0u
#define B0_OFF      20480u
#define STG_OFF     40960u
#define SMEM_BYTES  81920

__device__ __forceinline__ void issue_tile(
    uint32_t sA, uint32_t sB,
    const uint32_t* Ahi, const uint32_t* Alo,
    const uint32_t* Bhi, const uint32_t* Blo,
    int r0, int c0, int M, int Kp, int c, int tid)
{
#pragma unroll
    for (int p = 0; p < 2; p++) {
        int q   = p * 256 + tid;          // 0..511
        int row = q >> 2;                 // 0..127
        int u   = q & 3;                  // 16B chunk in 64B row
        uint32_t so = (uint32_t)((row * 20 + u * 4) * 4);
        // A (guard rows beyond M via src_size=0 zero-fill; clamp addr in-bounds)
        int ar = r0 + row;
        uint32_t sz = (ar < M) ? 16u : 0u;
        if (ar >= M) ar = 0;
        size_t ga = (size_t)ar * Kp + c * 16 + u * 4;
        cp16(sA + so,            &Ahi[ga], sz);
        cp16(sA + HILO_OFF + so, &Alo[ga], sz);
        // B (N multiple of 128, no guard)
        size_t gb = (size_t)(c0 + row) * Kp + c * 16 + u * 4;
        cp16(sB + so,            &Bhi[gb], 16u);
        cp16(sB + HILO_OFF + so, &Blo[gb], 16u);
    }
}

template<int ACT, bool ADD>
__global__ __launch_bounds__(256, 2) void bgemm(
    const uint32_t* __restrict__ Ahi, const uint32_t* __restrict__ Alo,
    const uint32_t* __restrict__ Bhi, const uint32_t* __restrict__ Blo,
    const float* __restrict__ bias,
    uint32_t* __restrict__ Chi, uint32_t* __restrict__ Clo,
    int M, int K, int N)
{
    extern __shared__ __align__(16) uint8_t smem[];
    const uint32_t sb = smem_u32(smem);

    const int tid  = threadIdx.x;
    const int wid  = tid >> 5;
    const int lane = tid & 31;
    const int tig  = lane & 3;
    const int wm   = wid & 1;            // warp row: 64 rows
    const int wn   = wid >> 1;           // warp col 0..3: 32 cols
    const int r0   = blockIdx.y * 128;
    const int c0   = blockIdx.x * 128;
    const int Kp   = K >> 1;
    const int nch  = Kp >> 4;            // tiles of 16 kpairs

    // ldmatrix lane selectors (identical math to the R10-validated kernel)
    const int a_row_in = ((lane >> 3) & 1) * 8 + (lane & 7);
    const int a_kp_sel = (lane >> 4) * 4;
    const int b_col_in = (lane >> 4) * 8 + (lane & 7);
    const int b_kp_sel = ((lane >> 3) & 1) * 4;
    const uint32_t aoff = (uint32_t)(((wm * 64 + a_row_in) * 20 + a_kp_sel) * 4);
    const uint32_t boff = (uint32_t)(((wn * 32 + b_col_in) * 20 + b_kp_sel) * 4);

    float acc[4][4][4];
#pragma unroll
    for (int mf = 0; mf < 4; mf++)
#pragma unroll
        for (int nf = 0; nf < 4; nf++)
#pragma unroll
            for (int i = 0; i < 4; i++) acc[mf][nf][i] = 0.f;

    // prologue: stage 0 loads
    issue_tile(sb + A0_OFF, sb + B0_OFF, Ahi, Alo, Bhi, Blo, r0, c0, M, Kp, 0, tid);
    cp_commit();

    for (int c = 0; c < nch; c++) {
        const uint32_t stg = (c & 1) ? STG_OFF : 0u;
        if (c + 1 < nch) {
            const uint32_t nst = ((c + 1) & 1) ? STG_OFF : 0u;
            issue_tile(sb + A0_OFF + nst, sb + B0_OFF + nst,
                       Ahi, Alo, Bhi, Blo, r0, c0, M, Kp, c + 1, tid);
            cp_commit();
            asm volatile("cp.async.wait_group 1;" ::: "memory");
        } else {
            asm volatile("cp.async.wait_group 0;" ::: "memory");
        }
        __syncthreads();

        const uint32_t aB = sb + A0_OFF + stg + aoff;
        const uint32_t bB = sb + B0_OFF + stg + boff;
#pragma unroll
        for (int k16 = 0; k16 < 2; k16++) {
            const uint32_t kof = (uint32_t)(k16 * 8 * 4);
            uint32_t ah[4][4], al[4][4];
#pragma unroll
            for (int mf = 0; mf < 4; mf++) {
                uint32_t adr = aB + kof + (uint32_t)(mf * 16 * 20 * 4);
                ldsm4(ah[mf][0], ah[mf][1], ah[mf][2], ah[mf][3], adr);
                ldsm4(al[mf][0], al[mf][1], al[mf][2], al[mf][3], adr + HILO_OFF);
            }
#pragma unroll
            for (int nfp = 0; nfp < 2; nfp++) {
                uint32_t bdr = bB + kof + (uint32_t)(nfp * 16 * 20 * 4);
                uint32_t bh[4], bl[4];
                ldsm4(bh[0], bh[1], bh[2], bh[3], bdr);
                ldsm4(bl[0], bl[1], bl[2], bl[3], bdr + HILO_OFF);
#pragma unroll
                for (int e = 0; e < 2; e++) {
                    const int nf = nfp * 2 + e;
#pragma unroll
                    for (int mf = 0; mf < 4; mf++) mma16(acc[mf][nf], ah[mf], &bh[e * 2]);
#pragma unroll
                    for (int mf = 0; mf < 4; mf++) mma16(acc[mf][nf], al[mf], &bh[e * 2]);
#pragma unroll
                    for (int mf = 0; mf < 4; mf++) mma16(acc[mf][nf], ah[mf], &bl[e * 2]);
                }
            }
        }
        __syncthreads();
    }

    // ---- epilogue: bias + act (+residual), split to bf16 pair, store --------
    const int Np = N >> 1;
#pragma unroll
    for (int mf = 0; mf < 4; mf++) {
#pragma unroll
        for (int nf = 0; nf < 4; nf++) {
            int gc = c0 + wn * 32 + nf * 8 + 2 * tig;
            int pc = gc >> 1;
            float bz0 = bias ? bias[gc]     : 0.f;
            float bz1 = bias ? bias[gc + 1] : 0.f;
#pragma unroll
            for (int half = 0; half < 2; half++) {
                int r = r0 + wm * 64 + mf * 16 + (lane >> 2) + half * 8;
                if (r >= M) continue;
                float v0 = act_apply<ACT>(acc[mf][nf][half * 2 + 0] + bz0);
                float v1 = act_apply<ACT>(acc[mf][nf][half * 2 + 1] + bz1);
                size_t idx = (size_t)r * Np + pc;
                if (ADD) {
                    float o0, o1;
                    recon2(Chi[idx], Clo[idx], o0, o1);
                    v0 += o0; v1 += o1;
                }
                uint32_t h, l;
                split2(v0, v1, h, l);
                Chi[idx] = h; Clo[idx] = l;
            }
        }
    }
}

// ---------------- fused weight pre-split (ONE launch for all 21 weights) ------
// W[K,N] fp32 -> hi/lo [N][K/2] n-major (bf16x2 packed along K).
struct SplitArgs {
    const float* W[21];
    uint32_t* hi[21];
    uint32_t* lo[21];
    int P[21];       // K/2
    int Nc[21];
    int start[22];   // prefix of blocks (256 elems each)
};
__global__ void k_splitW_all(SplitArgs a)
{
    int gb = blockIdx.x;
    int w = 0;
    while (gb >= a.start[w + 1]) w++;
    int idx = (gb - a.start[w]) * 256 + threadIdx.x;
    int P = a.P[w], Nc = a.Nc[w];
    if (idx >= P * Nc) return;
    int n = idx / P, p = idx - n * P;
    const float* W = a.W[w];
    float f0 = W[(size_t)(2 * p)     * Nc + n];
    float f1 = W[(size_t)(2 * p + 1) * Nc + n];
    uint32_t h, l;
    split2(f0, f1, h, l);
    a.hi[w][idx] = h; a.lo[w][idx] = l;
}

// ---------------- node embedding: z = cat(emb[at]+fr, fp-fr), packed ---------
__global__ void k_node_embed(const float* __restrict__ r_feat, const float* __restrict__ p_feat,
                             const float* __restrict__ emb, const float* __restrict__ Wf,
                             const int* __restrict__ at,
                             uint32_t* __restrict__ hhi, uint32_t* __restrict__ hlo)
{
    int n = blockIdx.x, c = threadIdx.x;        // 64 threads, pair of cols (2c,2c+1)
    __shared__ float rs[27], ps[27];
    if (c < 27) { rs[c] = r_feat[n * 27 + c]; ps[c] = p_feat[n * 27 + c]; }
    __syncthreads();
    float fr0 = 0.f, fr1 = 0.f, fp0 = 0.f, fp1 = 0.f;
#pragma unroll
    for (int k = 0; k < 27; k++) {
        float w0 = Wf[k * 128 + 2 * c], w1 = Wf[k * 128 + 2 * c + 1];
        fr0 = fmaf(rs[k], w0, fr0); fr1 = fmaf(rs[k], w1, fr1);
        fp0 = fmaf(ps[k], w0, fp0); fp1 = fmaf(ps[k], w1, fp1);
    }
    int t = at[n];
    float e0 = emb[t * 128 + 2 * c], e1 = emb[t * 128 + 2 * c + 1];
    uint32_t h, l;
    split2(e0 + fr0, e1 + fr1, h, l);
    hhi[(size_t)n * 128 + c] = h;  hlo[(size_t)n * 128 + c] = l;
    split2(fp0 - fr0, fp1 - fr1, h, l);
    hhi[(size_t)n * 128 + 64 + c] = h;  hlo[(size_t)n * 128 + 64 + c] = l;
}

// ---------------- edge length + silu(d*W1+b1), packed ------------------------
__global__ void k_edge_d_h1(const float* __restrict__ pos, const int* __restrict__ ei,
                            const float* __restrict__ W1, const float* __restrict__ b1,
                            float* __restrict__ dlen,
                            uint32_t* __restrict__ ohi, uint32_t* __restrict__ olo, int E)
{
    int e = blockIdx.x, c = threadIdx.x;        // 128 threads, cols (2c,2c+1)
    int s = ei[e], t = ei[E + e];
    float dx = pos[t * 3 + 0] - pos[s * 3 + 0];
    float dy = pos[t * 3 + 1] - pos[s * 3 + 1];
    float dz = pos[t * 3 + 2] - pos[s * 3 + 2];
    float d = sqrtf(dx * dx + dy * dy + dz * dz);
    if (c == 0) dlen[e] = d;
    float v0 = silu_f(fmaf(d, W1[2 * c], b1[2 * c]));
    float v1 = silu_f(fmaf(d, W1[2 * c + 1], b1[2 * c + 1]));
    uint32_t h, l;
    split2(v0, v1, h, l);
    ohi[(size_t)e * 128 + c] = h;  olo[(size_t)e * 128 + c] = l;
}

// ---------------- bond gating + concatenation, packed ------------------------
__global__ void k_bondgate(const uint32_t* __restrict__ mhi, const uint32_t* __restrict__ mlo,
                           const float* __restrict__ bemb,
                           const int* __restrict__ tr, const int* __restrict__ tp,
                           uint32_t* __restrict__ ohi, uint32_t* __restrict__ olo)
{
    int e = blockIdx.x, c = threadIdx.x;        // 128 threads
    float v0, v1;
    recon2(mhi[(size_t)e * 128 + c], mlo[(size_t)e * 128 + c], v0, v1);
    int ir = tr[e] * 256 + 2 * c, ip = tp[e] * 256 + 2 * c;
    uint32_t h, l;
    split2(v0 * bemb[ir], v1 * bemb[ir + 1], h, l);
    ohi[(size_t)e * 256 + c] = h;        olo[(size_t)e * 256 + c] = l;
    split2(v0 * bemb[ip], v1 * bemb[ip + 1], h, l);
    ohi[(size_t)e * 256 + 128 + c] = h;  olo[(size_t)e * 256 + 128 + c] = l;
}

// ---------------- deterministic gather aggregation (segment_sum), packed -----
// e = g*600 + i*24 + (j - (j > i)),  src = g*25 + i, dst = g*25 + j
__global__ void k_aggregate(const uint32_t* __restrict__ nhi, const uint32_t* __restrict__ nlo,
                            const uint32_t* __restrict__ whi, const uint32_t* __restrict__ wlo,
                            uint32_t* __restrict__ ahi, uint32_t* __restrict__ alo)
{
    int n = blockIdx.x, c = threadIdx.x;        // 128 threads = pairs
    int g = n / 25, j = n % 25;
    int base_e = g * 600, base_n = g * 25;
    float a0 = 0.f, a1 = 0.f;
#pragma unroll
    for (int i = 0; i < 25; i++) {
        if (i == j) continue;
        int e = base_e + i * 24 + (j - (int)(j > i));
        float x0, x1, w0, w1;
        recon2(nhi[(size_t)(base_n + i) * 128 + c], nlo[(size_t)(base_n + i) * 128 + c], x0, x1);
        recon2(whi[(size_t)e * 128 + c],            wlo[(size_t)e * 128 + c],            w0, w1);
        a0 = fmaf(x0, w0, a0);
        a1 = fmaf(x1, w1, a1);
    }
    uint32_t h, l;
    split2(a0, a1, h, l);
    ahi[(size_t)n * 128 + c] = h;  alo[(size_t)n * 128 + c] = l;
}

// ---------------- pair assembly, packed --------------------------------------
__global__ void k_pair(const uint32_t* __restrict__ hhi, const uint32_t* __restrict__ hlo,
                       const uint32_t* __restrict__ ehi, const uint32_t* __restrict__ elo,
                       const int* __restrict__ ei,
                       uint32_t* __restrict__ ohi, uint32_t* __restrict__ olo, int E)
{
    int e = blockIdx.x, c = threadIdx.x;        // 256 threads = 256 pairs
    if (c < 128) {
        int s = ei[e], t = ei[E + e];
        float s0, s1, t0, t1;
        recon2(hhi[(size_t)s * 128 + c], hlo[(size_t)s * 128 + c], s0, s1);
        recon2(hhi[(size_t)t * 128 + c], hlo[(size_t)t * 128 + c], t0, t1);
        uint32_t h, l;
        split2(s0 * t0, s1 * t1, h, l);
        ohi[(size_t)e * 256 + c] = h;  olo[(size_t)e * 256 + c] = l;
    } else {
        int c2 = c - 128;
        ohi[(size_t)e * 256 + c] = ehi[(size_t)e * 128 + c2];
        olo[(size_t)e * 256 + c] = elo[(size_t)e * 128 + c2];
    }
}

// ---------------- final projection [E,128] @ [128,1] + b ---------------------
__global__ void k_final(const uint32_t* __restrict__ xhi, const uint32_t* __restrict__ xlo,
                        const float* __restrict__ W3, const float* __restrict__ b3,
                        float* __restrict__ out, int E)
{
    int e = blockIdx.x * 8 + (threadIdx.x >> 5);
    int lane = threadIdx.x & 31;
    if (e >= E) return;
    float acc = 0.f;
#pragma unroll
    for (int q = 0; q < 2; q++) {
        int p = q * 32 + lane;
        float v0, v1;
        recon2(xhi[(size_t)e * 64 + p], xlo[(size_t)e * 64 + p], v0, v1);
        acc = fmaf(v0, W3[2 * p], acc);
        acc = fmaf(v1, W3[2 * p + 1], acc);
    }
#pragma unroll
    for (int o = 16; o; o >>= 1) acc += __shfl_xor_sync(0xffffffffu, acc, o);
    if (lane == 0) out[e] = acc + b3[0];
}

// ---------------- extra outputs (edge_index as float, d) ---------------------
__global__ void k_extras(const int* __restrict__ ei, const float* __restrict__ dlen,
                         float* __restrict__ out, int E)
{
    int k = blockIdx.x * 256 + threadIdx.x;
    if (k < 2 * E) out[E + k] = (float)ei[k];
    if (k < E)     out[3 * E + k] = dlen[k];
}

// ---------------- GEMM dispatch ----------------------------------------------
static void gemm(const uint32_t* Ahi, const uint32_t* Alo,
                 const uint32_t* Bhi, const uint32_t* Blo,
                 const float* bias, uint32_t* Chi, uint32_t* Clo,
                 int M, int K, int N, int act, bool add)
{
    dim3 grid(N / 128, (M + 127) / 128);
    if (add) {
        cudaFuncSetAttribute((const void*)bgemm<2, true>,
                             cudaFuncAttributeMaxDynamicSharedMemorySize, SMEM_BYTES);
        bgemm<2, true><<<grid, 256, SMEM_BYTES>>>(Ahi, Alo, Bhi, Blo, bias, Chi, Clo, M, K, N);
        return;
    }
    switch (act) {
        case 0:
            cudaFuncSetAttribute((const void*)bgemm<0, false>,
                                 cudaFuncAttributeMaxDynamicSharedMemorySize, SMEM_BYTES);
            bgemm<0, false><<<grid, 256, SMEM_BYTES>>>(Ahi, Alo, Bhi, Blo, bias, Chi, Clo, M, K, N);
            break;
        case 1:
            cudaFuncSetAttribute((const void*)bgemm<1, false>,
                                 cudaFuncAttributeMaxDynamicSharedMemorySize, SMEM_BYTES);
            bgemm<1, false><<<grid, 256, SMEM_BYTES>>>(Ahi, Alo, Bhi, Blo, bias, Chi, Clo, M, K, N);
            break;
        case 2:
            cudaFuncSetAttribute((const void*)bgemm<2, false>,
                                 cudaFuncAttributeMaxDynamicSharedMemorySize, SMEM_BYTES);
            bgemm<2, false><<<grid, 256, SMEM_BYTES>>>(Ahi, Alo, Bhi, Blo, bias, Chi, Clo, M, K, N);
            break;
    }
}

extern "C" void kernel_launch(void* const* d_in, const int* in_sizes, int n_in,
                              void* d_out, int out_size)
{
    const float* pos      = (const float*)d_in[0];
    const float* r_feat   = (const float*)d_in[1];
    const float* p_feat   = (const float*)d_in[2];
    const float* emb_tab  = (const float*)d_in[3];
    const float* feat_W   = (const float*)d_in[4];
    const float* bond_emb = (const float*)d_in[5];
    const float* ee_W1    = (const float*)d_in[6];
    const float* ee_b1    = (const float*)d_in[7];
    const float* ee_W2    = (const float*)d_in[8];
    const float* ee_b2    = (const float*)d_in[9];
    const float* ec_W1    = (const float*)d_in[10];
    const float* ec_b1    = (const float*)d_in[11];
    const float* ec_W2    = (const float*)d_in[12];
    const float* ec_b2    = (const float*)d_in[13];
    const float* fW1      = (const float*)d_in[14];
    const float* fb1      = (const float*)d_in[15];
    const float* fW2      = (const float*)d_in[16];
    const float* fb2      = (const float*)d_in[17];
    const float* lin1     = (const float*)d_in[18];
    const float* lin2     = (const float*)d_in[19];
    const float* lin2b    = (const float*)d_in[20];
    const float* g_W1     = (const float*)d_in[21];
    const float* g_b1     = (const float*)d_in[22];
    const float* g_W2     = (const float*)d_in[23];
    const float* g_b2     = (const float*)d_in[24];
    const float* g_W3     = (const float*)d_in[25];
    const float* g_b3     = (const float*)d_in[26];
    const int*   at       = (const int*)d_in[27];
    const int*   ei       = (const int*)d_in[28];
    const int*   tr       = (const int*)d_in[29];
    const int*   tp       = (const int*)d_in[30];

    const int N = in_sizes[0] / 3;     // nodes
    const int E = in_sizes[28] / 2;    // edges

    uint32_t *pcat_hi, *pcat_lo, *pe1_hi, *pe1_lo, *pe2_hi, *pe2_lo;
    uint32_t *pat_hi, *pat_lo, *ph_hi, *ph_lo, *pnt_hi, *pnt_lo, *pag_hi, *pag_lo, *wsplit;
    float *dlen;
    cudaGetSymbolAddress((void**)&pcat_hi, g_pcat_hi);
    cudaGetSymbolAddress((void**)&pcat_lo, g_pcat_lo);
    cudaGetSymbolAddress((void**)&pe1_hi,  g_pe1_hi);
    cudaGetSymbolAddress((void**)&pe1_lo,  g_pe1_lo);
    cudaGetSymbolAddress((void**)&pe2_hi,  g_pe2_hi);
    cudaGetSymbolAddress((void**)&pe2_lo,  g_pe2_lo);
    cudaGetSymbolAddress((void**)&pat_hi,  g_pat_hi);
    cudaGetSymbolAddress((void**)&pat_lo,  g_pat_lo);
    cudaGetSymbolAddress((void**)&ph_hi,   g_ph_hi);
    cudaGetSymbolAddress((void**)&ph_lo,   g_ph_lo);
    cudaGetSymbolAddress((void**)&pnt_hi,  g_pnt_hi);
    cudaGetSymbolAddress((void**)&pnt_lo,  g_pnt_lo);
    cudaGetSymbolAddress((void**)&pag_hi,  g_pag_hi);
    cudaGetSymbolAddress((void**)&pag_lo,  g_pag_lo);
    cudaGetSymbolAddress((void**)&wsplit,  g_wsplit);
    cudaGetSymbolAddress((void**)&dlen,    g_dlen);

    float* out = (float*)d_out;

    // ---- pre-split all GEMM weights in ONE launch (bf16 hi/lo, n-major) -----
    // Index map: 0..2 edge-embedding, 3..18 conv (4/layer), 19 g_W1, 20 g_W2.
    SplitArgs sa;
    const uint32_t* Wh[21]; const uint32_t* Wl[21];
    {
        size_t off = 0;
        int blk = 0;
        auto reg = [&](int idx, const float* W, int K, int Nc) {
            int P = K / 2;
            size_t S = (size_t)P * Nc;
            sa.W[idx]  = W;
            sa.hi[idx] = wsplit + off;
            sa.lo[idx] = wsplit + off + S;
            sa.P[idx]  = P;
            sa.Nc[idx] = Nc;
            sa.start[idx] = blk;
            Wh[idx] = sa.hi[idx]; Wl[idx] = sa.lo[idx];
            blk += (int)((S + 255) / 256);
            off += 2 * S;
        };
        reg(0, ee_W2, 256, 256);
        reg(1, ec_W1, 512, 256);
        reg(2, ec_W2, 256, 256);
        for (int l = 0; l < 4; l++) {
            reg(3 + l * 4 + 0, fW1  + (size_t)l * 65536, 256, 256);
            reg(3 + l * 4 + 1, fW2  + (size_t)l * 65536, 256, 256);
            reg(3 + l * 4 + 2, lin1 + (size_t)l * 65536, 256, 256);
            reg(3 + l * 4 + 3, lin2 + (size_t)l * 65536, 256, 256);
        }
        reg(19, g_W1, 512, 256);
        reg(20, g_W2, 256, 128);
        sa.start[21] = blk;
        k_splitW_all<<<blk, 256>>>(sa);
    }

    // 1) node embedding -> ph (packed)
    k_node_embed<<<N, 64>>>(r_feat, p_feat, emb_tab, feat_W, at, ph_hi, ph_lo);

    // 2) edge length + silu(d*W1+b1) -> pe1
    k_edge_d_h1<<<E, 128>>>(pos, ei, ee_W1, ee_b1, dlen, pe1_hi, pe1_lo, E);

    // 3) mlp_d = pe1 @ ee_W2 + ee_b2 -> pe2
    gemm(pe1_hi, pe1_lo, Wh[0], Wl[0], ee_b2, pe2_hi, pe2_lo, E, 256, 256, 0, false);

    // 4) gate by bond embeddings, cat(r,p) -> pcat (512-wide)
    k_bondgate<<<E, 128>>>(pe2_hi, pe2_lo, bond_emb, tr, tp, pcat_hi, pcat_lo);

    // 5) edge_attr = silu(pcat @ ec_W1 + b1) @ ec_W2 + b2 -> pat
    gemm(pcat_hi, pcat_lo, Wh[1], Wl[1], ec_b1, pe1_hi, pe1_lo, E, 512, 256, 1, false);
    gemm(pe1_hi, pe1_lo, Wh[2], Wl[2], ec_b2, pat_hi, pat_lo, E, 256, 256, 0, false);

    // 6) 4 CFConv interaction blocks
    for (int l = 0; l < 4; l++) {
        const float* b1  = fb1  + (size_t)l * 256;
        const float* b2  = fb2  + (size_t)l * 256;
        const float* l2b = lin2b + (size_t)l * 256;
        int wi = 3 + l * 4;

        gemm(pat_hi, pat_lo, Wh[wi + 0], Wl[wi + 0], b1, pe1_hi, pe1_lo, E, 256, 256, 2, false);
        gemm(pe1_hi, pe1_lo, Wh[wi + 1], Wl[wi + 1], b2, pe2_hi, pe2_lo, E, 256, 256, 0, false);
        gemm(ph_hi, ph_lo, Wh[wi + 2], Wl[wi + 2], nullptr, pnt_hi, pnt_lo, N, 256, 256, 0, false);
        k_aggregate<<<N, 128>>>(pnt_hi, pnt_lo, pe2_hi, pe2_lo, pag_hi, pag_lo);
        gemm(pag_hi, pag_lo, Wh[wi + 3], Wl[wi + 3], l2b, ph_hi, ph_lo, N, 256, 256, 2, true);
    }

    // 7) pair features -> pcat
    k_pair<<<E, 256>>>(ph_hi, ph_lo, pat_hi, pat_lo, ei, pcat_hi, pcat_lo, E);

    // 8) output head
    gemm(pcat_hi, pcat_lo, Wh[19], Wl[19], g_b1, pe1_hi, pe1_lo, E, 512, 256, 1, false);
    gemm(pe1_hi, pe1_lo, Wh[20], Wl[20], g_b2, pe2_hi, pe2_lo, E, 256, 128, 1, false);
    k_final<<<(E + 7) / 8, 256>>>(pe2_hi, pe2_lo, g_W3, g_b3, out, E);

    // 9) remaining tuple outputs (edge_index, d) if compared
    if (out_size >= 4 * E) {
        k_extras<<<(2 * E + 255) / 256, 256>>>(ei, dlen, out, E);
    }
}

// round 13
// speedup vs baseline: 1.2554x; 1.0126x over previous
#include <cuda_runtime.h>
#include <math.h>
#include <stdint.h>

// Fixed problem sizes (guarded at runtime by in_sizes)
#define EMAX 120000
#define NMAX 5000

// ---------------- scratch (device globals; no allocation allowed) ------------
__device__ uint32_t g_pcat_hi[(size_t)EMAX * 256], g_pcat_lo[(size_t)EMAX * 256]; // 512-wide
__device__ uint32_t g_pe1_hi [(size_t)EMAX * 128], g_pe1_lo [(size_t)EMAX * 128]; // 256-wide
__device__ uint32_t g_pe2_hi [(size_t)EMAX * 128], g_pe2_lo [(size_t)EMAX * 128];
__device__ uint32_t g_pat_hi [(size_t)EMAX * 128], g_pat_lo [(size_t)EMAX * 128];
__device__ uint32_t g_ph_hi  [(size_t)NMAX * 128], g_ph_lo  [(size_t)NMAX * 128];
__device__ uint32_t g_pnt_hi [(size_t)NMAX * 128], g_pnt_lo [(size_t)NMAX * 128];
__device__ uint32_t g_pag_hi [(size_t)NMAX * 128], g_pag_lo [(size_t)NMAX * 128];
__device__ float    g_dlen[EMAX];
__device__ uint32_t g_wsplit[1600000];   // pre-split weights (bf16 hi/lo, n-major)

// ---------------- activations ------------------------------------------------
__device__ __forceinline__ float silu_f(float x) { return x / (1.f + expf(-x)); }
__device__ __forceinline__ float ssp_f(float x) {
    float sp = (x > 15.f) ? x : log1pf(expf(x));
    return sp - 0.69314718056f;
}
template<int ACT>
__device__ __forceinline__ float act_apply(float x) {
    if (ACT == 1) return silu_f(x);
    if (ACT == 2) return ssp_f(x);
    return x;
}

// ---------------- bf16 pair pack / split / reconstruct -----------------------
__device__ __forceinline__ uint32_t pack2(float f0, float f1) {
    uint32_t r;
    asm("cvt.rn.bf16x2.f32 %0, %1, %2;" : "=r"(r) : "f"(f1), "f"(f0));
    return r;
}
__device__ __forceinline__ void split2(float f0, float f1, uint32_t& hi, uint32_t& lo) {
    hi = pack2(f0, f1);
    float h0 = __uint_as_float(hi << 16);
    float h1 = __uint_as_float(hi & 0xffff0000u);
    lo = pack2(f0 - h0, f1 - h1);
}
__device__ __forceinline__ void recon2(uint32_t hi, uint32_t lo, float& f0, float& f1) {
    f0 = __uint_as_float(hi << 16)        + __uint_as_float(lo << 16);
    f1 = __uint_as_float(hi & 0xffff0000u) + __uint_as_float(lo & 0xffff0000u);
}

// ---------------- mma / ldmatrix / cp.async -----------------------------------
__device__ __forceinline__ void mma16(float* d, const uint32_t* a, const uint32_t* b) {
    asm volatile(
        "mma.sync.aligned.m16n8k16.row.col.f32.bf16.bf16.f32 "
        "{%0,%1,%2,%3}, {%4,%5,%6,%7}, {%8,%9}, {%0,%1,%2,%3};"
        : "+f"(d[0]), "+f"(d[1]), "+f"(d[2]), "+f"(d[3])
        : "r"(a[0]), "r"(a[1]), "r"(a[2]), "r"(a[3]), "r"(b[0]), "r"(b[1]));
}
__device__ __forceinline__ void ldsm4(uint32_t& r0, uint32_t& r1, uint32_t& r2, uint32_t& r3,
                                      uint32_t saddr) {
    asm volatile("ldmatrix.sync.aligned.m8n8.x4.shared.b16 {%0,%1,%2,%3}, [%4];"
                 : "=r"(r0), "=r"(r1), "=r"(r2), "=r"(r3) : "r"(saddr));
}
__device__ __forceinline__ void cp16(uint32_t sdst, const void* gsrc, uint32_t sz) {
    asm volatile("cp.async.cg.shared.global [%0], [%1], 16, %2;"
                 :: "r"(sdst), "l"(gsrc), "r"(sz) : "memory");
}
__device__ __forceinline__ void cp_commit() {
    asm volatile("cp.async.commit_group;" ::: "memory");
}
__device__ __forceinline__ uint32_t smem_u32(const void* p) {
    uint32_t a;
    asm("{ .reg .u64 t; cvta.to.shared.u64 t, %1; cvt.u32.u64 %0, t; }" : "=r"(a) : "l"(p));
    return a;
}

// ---------------- bf16x3 tensor-core GEMM, cp.async double-buffered -----------
// C = act(A @ B + bias) via Ahi@Bhi + Alo@Bhi + Ahi@Blo (fp32 acc).
// A packed [M][K/2] u32 (bf16x2 k-major). B (weights) packed [Ntot][K/2] (n-major).
// BM=BN=128, tile = 16 kpairs (32 bf16). 256 threads = 8 warps (2x4), warp 64x32.
// GATE variant (step 3 fusion): output = cat(v*bemb[tr], v*bemb[tp]) pair-packed
// into a 512-wide buffer (256 pairs/row).
#define HILO_OFF    10240u                // 128*20*4 bytes
#define A0_OFF      0u
#define B0_OFF      20480u
#define STG_OFF     40960u
#define SMEM_BYTES  81920

__device__ __forceinline__ void issue_tile(
    uint32_t sA, uint32_t sB,
    const uint32_t* Ahi, const uint32_t* Alo,
    const uint32_t* Bhi, const uint32_t* Blo,
    int r0, int c0, int M, int Kp, int c, int tid)
{
#pragma unroll
    for (int p = 0; p < 2; p++) {
        int q   = p * 256 + tid;          // 0..511
        int row = q >> 2;                 // 0..127
        int u   = q & 3;                  // 16B chunk in 64B row
        uint32_t so = (uint32_t)((row * 20 + u * 4) * 4);
        int ar = r0 + row;
        uint32_t sz = (ar < M) ? 16u : 0u;
        if (ar >= M) ar = 0;
        size_t ga = (size_t)ar * Kp + c * 16 + u * 4;
        cp16(sA + so,            &Ahi[ga], sz);
        cp16(sA + HILO_OFF + so, &Alo[ga], sz);
        size_t gb = (size_t)(c0 + row) * Kp + c * 16 + u * 4;
        cp16(sB + so,            &Bhi[gb], 16u);
        cp16(sB + HILO_OFF + so, &Blo[gb], 16u);
    }
}

template<int ACT, bool ADD, bool GATE>
__global__ __launch_bounds__(256, 2) void bgemm(
    const uint32_t* __restrict__ Ahi, const uint32_t* __restrict__ Alo,
    const uint32_t* __restrict__ Bhi, const uint32_t* __restrict__ Blo,
    const float* __restrict__ bias,
    uint32_t* __restrict__ Chi, uint32_t* __restrict__ Clo,
    int M, int K, int N,
    const float* __restrict__ bemb, const int* __restrict__ tr, const int* __restrict__ tp)
{
    extern __shared__ __align__(16) uint8_t smem[];
    const uint32_t sb = smem_u32(smem);

    const int tid  = threadIdx.x;
    const int wid  = tid >> 5;
    const int lane = tid & 31;
    const int tig  = lane & 3;
    const int wm   = wid & 1;            // warp row: 64 rows
    const int wn   = wid >> 1;           // warp col 0..3: 32 cols
    const int r0   = blockIdx.y * 128;
    const int c0   = blockIdx.x * 128;
    const int Kp   = K >> 1;
    const int nch  = Kp >> 4;            // tiles of 16 kpairs

    const int a_row_in = ((lane >> 3) & 1) * 8 + (lane & 7);
    const int a_kp_sel = (lane >> 4) * 4;
    const int b_col_in = (lane >> 4) * 8 + (lane & 7);
    const int b_kp_sel = ((lane >> 3) & 1) * 4;
    const uint32_t aoff = (uint32_t)(((wm * 64 + a_row_in) * 20 + a_kp_sel) * 4);
    const uint32_t boff = (uint32_t)(((wn * 32 + b_col_in) * 20 + b_kp_sel) * 4);

    float acc[4][4][4];
#pragma unroll
    for (int mf = 0; mf < 4; mf++)
#pragma unroll
        for (int nf = 0; nf < 4; nf++)
#pragma unroll
            for (int i = 0; i < 4; i++) acc[mf][nf][i] = 0.f;

    issue_tile(sb + A0_OFF, sb + B0_OFF, Ahi, Alo, Bhi, Blo, r0, c0, M, Kp, 0, tid);
    cp_commit();

    for (int c = 0; c < nch; c++) {
        const uint32_t stg = (c & 1) ? STG_OFF : 0u;
        if (c + 1 < nch) {
            const uint32_t nst = ((c + 1) & 1) ? STG_OFF : 0u;
            issue_tile(sb + A0_OFF + nst, sb + B0_OFF + nst,
                       Ahi, Alo, Bhi, Blo, r0, c0, M, Kp, c + 1, tid);
            cp_commit();
            asm volatile("cp.async.wait_group 1;" ::: "memory");
        } else {
            asm volatile("cp.async.wait_group 0;" ::: "memory");
        }
        __syncthreads();

        const uint32_t aB = sb + A0_OFF + stg + aoff;
        const uint32_t bB = sb + B0_OFF + stg + boff;
#pragma unroll
        for (int k16 = 0; k16 < 2; k16++) {
            const uint32_t kof = (uint32_t)(k16 * 8 * 4);
            uint32_t ah[4][4], al[4][4];
#pragma unroll
            for (int mf = 0; mf < 4; mf++) {
                uint32_t adr = aB + kof + (uint32_t)(mf * 16 * 20 * 4);
                ldsm4(ah[mf][0], ah[mf][1], ah[mf][2], ah[mf][3], adr);
                ldsm4(al[mf][0], al[mf][1], al[mf][2], al[mf][3], adr + HILO_OFF);
            }
#pragma unroll
            for (int nfp = 0; nfp < 2; nfp++) {
                uint32_t bdr = bB + kof + (uint32_t)(nfp * 16 * 20 * 4);
                uint32_t bh[4], bl[4];
                ldsm4(bh[0], bh[1], bh[2], bh[3], bdr);
                ldsm4(bl[0], bl[1], bl[2], bl[3], bdr + HILO_OFF);
                // pass-major order: dependent MMAs on one acc are 8 issues apart
#pragma unroll
                for (int e = 0; e < 2; e++)
#pragma unroll
                    for (int mf = 0; mf < 4; mf++)
                        mma16(acc[mf][nfp * 2 + e], ah[mf], &bh[e * 2]);
#pragma unroll
                for (int e = 0; e < 2; e++)
#pragma unroll
                    for (int mf = 0; mf < 4; mf++)
                        mma16(acc[mf][nfp * 2 + e], al[mf], &bh[e * 2]);
#pragma unroll
                for (int e = 0; e < 2; e++)
#pragma unroll
                    for (int mf = 0; mf < 4; mf++)
                        mma16(acc[mf][nfp * 2 + e], ah[mf], &bl[e * 2]);
            }
        }
        __syncthreads();
    }

    // ---- epilogue ------------------------------------------------------------
    const int Np = N >> 1;
#pragma unroll
    for (int mf = 0; mf < 4; mf++) {
#pragma unroll
        for (int nf = 0; nf < 4; nf++) {
            int gc = c0 + wn * 32 + nf * 8 + 2 * tig;
            int pc = gc >> 1;
            float bz0 = bias ? bias[gc]     : 0.f;
            float bz1 = bias ? bias[gc + 1] : 0.f;
#pragma unroll
            for (int half = 0; half < 2; half++) {
                int r = r0 + wm * 64 + mf * 16 + (lane >> 2) + half * 8;
                if (r >= M) continue;
                float v0 = act_apply<ACT>(acc[mf][nf][half * 2 + 0] + bz0);
                float v1 = act_apply<ACT>(acc[mf][nf][half * 2 + 1] + bz1);
                if (GATE) {
                    // fused bond gating + concatenation into 512-wide buffer
                    int ir = tr[r] * 256 + gc, ip = tp[r] * 256 + gc;
                    uint32_t h, l;
                    size_t base = (size_t)r * 256 + pc;
                    split2(v0 * bemb[ir], v1 * bemb[ir + 1], h, l);
                    Chi[base] = h;        Clo[base] = l;
                    split2(v0 * bemb[ip], v1 * bemb[ip + 1], h, l);
                    Chi[base + 128] = h;  Clo[base + 128] = l;
                } else {
                    size_t idx = (size_t)r * Np + pc;
                    if (ADD) {
                        float o0, o1;
                        recon2(Chi[idx], Clo[idx], o0, o1);
                        v0 += o0; v1 += o1;
                    }
                    uint32_t h, l;
                    split2(v0, v1, h, l);
                    Chi[idx] = h; Clo[idx] = l;
                }
            }
        }
    }
}

// ---------------- fused weight pre-split (ONE launch for all 21 weights) ------
struct SplitArgs {
    const float* W[21];
    uint32_t* hi[21];
    uint32_t* lo[21];
    int P[21];       // K/2
    int Nc[21];
    int start[22];   // prefix of blocks (256 elems each)
};
__global__ void k_splitW_all(SplitArgs a)
{
    int gb = blockIdx.x;
    int w = 0;
    while (gb >= a.start[w + 1]) w++;
    int idx = (gb - a.start[w]) * 256 + threadIdx.x;
    int P = a.P[w], Nc = a.Nc[w];
    if (idx >= P * Nc) return;
    int n = idx / P, p = idx - n * P;
    const float* W = a.W[w];
    float f0 = W[(size_t)(2 * p)     * Nc + n];
    float f1 = W[(size_t)(2 * p + 1) * Nc + n];
    uint32_t h, l;
    split2(f0, f1, h, l);
    a.hi[w][idx] = h; a.lo[w][idx] = l;
}

// ---------------- node embedding: z = cat(emb[at]+fr, fp-fr), packed ---------
__global__ void k_node_embed(const float* __restrict__ r_feat, const float* __restrict__ p_feat,
                             const float* __restrict__ emb, const float* __restrict__ Wf,
                             const int* __restrict__ at,
                             uint32_t* __restrict__ hhi, uint32_t* __restrict__ hlo)
{
    int n = blockIdx.x, c = threadIdx.x;        // 64 threads, pair of cols (2c,2c+1)
    __shared__ float rs[27], ps[27];
    if (c < 27) { rs[c] = r_feat[n * 27 + c]; ps[c] = p_feat[n * 27 + c]; }
    __syncthreads();
    float fr0 = 0.f, fr1 = 0.f, fp0 = 0.f, fp1 = 0.f;
#pragma unroll
    for (int k = 0; k < 27; k++) {
        float w0 = Wf[k * 128 + 2 * c], w1 = Wf[k * 128 + 2 * c + 1];
        fr0 = fmaf(rs[k], w0, fr0); fr1 = fmaf(rs[k], w1, fr1);
        fp0 = fmaf(ps[k], w0, fp0); fp1 = fmaf(ps[k], w1, fp1);
    }
    int t = at[n];
    float e0 = emb[t * 128 + 2 * c], e1 = emb[t * 128 + 2 * c + 1];
    uint32_t h, l;
    split2(e0 + fr0, e1 + fr1, h, l);
    hhi[(size_t)n * 128 + c] = h;  hlo[(size_t)n * 128 + c] = l;
    split2(fp0 - fr0, fp1 - fr1, h, l);
    hhi[(size_t)n * 128 + 64 + c] = h;  hlo[(size_t)n * 128 + 64 + c] = l;
}

// ---------------- edge length + silu(d*W1+b1), packed ------------------------
__global__ void k_edge_d_h1(const float* __restrict__ pos, const int* __restrict__ ei,
                            const float* __restrict__ W1, const float* __restrict__ b1,
                            float* __restrict__ dlen,
                            uint32_t* __restrict__ ohi, uint32_t* __restrict__ olo, int E)
{
    int e = blockIdx.x, c = threadIdx.x;        // 128 threads, cols (2c,2c+1)
    int s = ei[e], t = ei[E + e];
    float dx = pos[t * 3 + 0] - pos[s * 3 + 0];
    float dy = pos[t * 3 + 1] - pos[s * 3 + 1];
    float dz = pos[t * 3 + 2] - pos[s * 3 + 2];
    float d = sqrtf(dx * dx + dy * dy + dz * dz);
    if (c == 0) dlen[e] = d;
    float v0 = silu_f(fmaf(d, W1[2 * c], b1[2 * c]));
    float v1 = silu_f(fmaf(d, W1[2 * c + 1], b1[2 * c + 1]));
    uint32_t h, l;
    split2(v0, v1, h, l);
    ohi[(size_t)e * 128 + c] = h;  olo[(size_t)e * 128 + c] = l;
}

// ---------------- deterministic gather aggregation (segment_sum), packed -----
// e = g*600 + i*24 + (j - (j > i)),  src = g*25 + i, dst = g*25 + j
__global__ void k_aggregate(const uint32_t* __restrict__ nhi, const uint32_t* __restrict__ nlo,
                            const uint32_t* __restrict__ whi, const uint32_t* __restrict__ wlo,
                            uint32_t* __restrict__ ahi, uint32_t* __restrict__ alo)
{
    int n = blockIdx.x, c = threadIdx.x;        // 128 threads = pairs
    int g = n / 25, j = n % 25;
    int base_e = g * 600, base_n = g * 25;
    float a0 = 0.f, a1 = 0.f;
#pragma unroll
    for (int i = 0; i < 25; i++) {
        if (i == j) continue;
        int e = base_e + i * 24 + (j - (int)(j > i));
        float x0, x1, w0, w1;
        recon2(nhi[(size_t)(base_n + i) * 128 + c], nlo[(size_t)(base_n + i) * 128 + c], x0, x1);
        recon2(whi[(size_t)e * 128 + c],            wlo[(size_t)e * 128 + c],            w0, w1);
        a0 = fmaf(x0, w0, a0);
        a1 = fmaf(x1, w1, a1);
    }
    uint32_t h, l;
    split2(a0, a1, h, l);
    ahi[(size_t)n * 128 + c] = h;  alo[(size_t)n * 128 + c] = l;
}

// ---------------- pair assembly, packed --------------------------------------
__global__ void k_pair(const uint32_t* __restrict__ hhi, const uint32_t* __restrict__ hlo,
                       const uint32_t* __restrict__ ehi, const uint32_t* __restrict__ elo,
                       const int* __restrict__ ei,
                       uint32_t* __restrict__ ohi, uint32_t* __restrict__ olo, int E)
{
    int e = blockIdx.x, c = threadIdx.x;        // 256 threads = 256 pairs
    if (c < 128) {
        int s = ei[e], t = ei[E + e];
        float s0, s1, t0, t1;
        recon2(hhi[(size_t)s * 128 + c], hlo[(size_t)s * 128 + c], s0, s1);
        recon2(hhi[(size_t)t * 128 + c], hlo[(size_t)t * 128 + c], t0, t1);
        uint32_t h, l;
        split2(s0 * t0, s1 * t1, h, l);
        ohi[(size_t)e * 256 + c] = h;  olo[(size_t)e * 256 + c] = l;
    } else {
        int c2 = c - 128;
        ohi[(size_t)e * 256 + c] = ehi[(size_t)e * 128 + c2];
        olo[(size_t)e * 256 + c] = elo[(size_t)e * 128 + c2];
    }
}

// ---------------- final projection [E,128] @ [128,1] + b ---------------------
__global__ void k_final(const uint32_t* __restrict__ xhi, const uint32_t* __restrict__ xlo,
                        const float* __restrict__ W3, const float* __restrict__ b3,
                        float* __restrict__ out, int E)
{
    int e = blockIdx.x * 8 + (threadIdx.x >> 5);
    int lane = threadIdx.x & 31;
    if (e >= E) return;
    float acc = 0.f;
#pragma unroll
    for (int q = 0; q < 2; q++) {
        int p = q * 32 + lane;
        float v0, v1;
        recon2(xhi[(size_t)e * 64 + p], xlo[(size_t)e * 64 + p], v0, v1);
        acc = fmaf(v0, W3[2 * p], acc);
        acc = fmaf(v1, W3[2 * p + 1], acc);
    }
#pragma unroll
    for (int o = 16; o; o >>= 1) acc += __shfl_xor_sync(0xffffffffu, acc, o);
    if (lane == 0) out[e] = acc + b3[0];
}

// ---------------- extra outputs (edge_index as float, d) ---------------------
__global__ void k_extras(const int* __restrict__ ei, const float* __restrict__ dlen,
                         float* __restrict__ out, int E)
{
    int k = blockIdx.x * 256 + threadIdx.x;
    if (k < 2 * E) out[E + k] = (float)ei[k];
    if (k < E)     out[3 * E + k] = dlen[k];
}

// ---------------- GEMM dispatch ----------------------------------------------
template<int ACT, bool ADD, bool GATE>
static void launch_gemm(const uint32_t* Ahi, const uint32_t* Alo,
                        const uint32_t* Bhi, const uint32_t* Blo,
                        const float* bias, uint32_t* Chi, uint32_t* Clo,
                        int M, int K, int N,
                        const float* bemb, const int* tr, const int* tp)
{
    dim3 grid(N / 128, (M + 127) / 128);
    cudaFuncSetAttribute((const void*)bgemm<ACT, ADD, GATE>,
                         cudaFuncAttributeMaxDynamicSharedMemorySize, SMEM_BYTES);
    bgemm<ACT, ADD, GATE><<<grid, 256, SMEM_BYTES>>>(
        Ahi, Alo, Bhi, Blo, bias, Chi, Clo, M, K, N, bemb, tr, tp);
}
static void gemm(const uint32_t* Ahi, const uint32_t* Alo,
                 const uint32_t* Bhi, const uint32_t* Blo,
                 const float* bias, uint32_t* Chi, uint32_t* Clo,
                 int M, int K, int N, int act, bool add)
{
    if (add) { launch_gemm<2, true, false>(Ahi, Alo, Bhi, Blo, bias, Chi, Clo, M, K, N, 0, 0, 0); return; }
    switch (act) {
        case 0: launch_gemm<0, false, false>(Ahi, Alo, Bhi, Blo, bias, Chi, Clo, M, K, N, 0, 0, 0); break;
        case 1: launch_gemm<1, false, false>(Ahi, Alo, Bhi, Blo, bias, Chi, Clo, M, K, N, 0, 0, 0); break;
        case 2: launch_gemm<2, false, false>(Ahi, Alo, Bhi, Blo, bias, Chi, Clo, M, K, N, 0, 0, 0); break;
    }
}

extern "C" void kernel_launch(void* const* d_in, const int* in_sizes, int n_in,
                              void* d_out, int out_size)
{
    const float* pos      = (const float*)d_in[0];
    const float* r_feat   = (const float*)d_in[1];
    const float* p_feat   = (const float*)d_in[2];
    const float* emb_tab  = (const float*)d_in[3];
    const float* feat_W   = (const float*)d_in[4];
    const float* bond_emb = (const float*)d_in[5];
    const float* ee_W1    = (const float*)d_in[6];
    const float* ee_b1    = (const float*)d_in[7];
    const float* ee_W2    = (const float*)d_in[8];
    const float* ee_b2    = (const float*)d_in[9];
    const float* ec_W1    = (const float*)d_in[10];
    const float* ec_b1    = (const float*)d_in[11];
    const float* ec_W2    = (const float*)d_in[12];
    const float* ec_b2    = (const float*)d_in[13];
    const float* fW1      = (const float*)d_in[14];
    const float* fb1      = (const float*)d_in[15];
    const float* fW2      = (const float*)d_in[16];
    const float* fb2      = (const float*)d_in[17];
    const float* lin1     = (const float*)d_in[18];
    const float* lin2     = (const float*)d_in[19];
    const float* lin2b    = (const float*)d_in[20];
    const float* g_W1     = (const float*)d_in[21];
    const float* g_b1     = (const float*)d_in[22];
    const float* g_W2     = (const float*)d_in[23];
    const float* g_b2     = (const float*)d_in[24];
    const float* g_W3     = (const float*)d_in[25];
    const float* g_b3     = (const float*)d_in[26];
    const int*   at       = (const int*)d_in[27];
    const int*   ei       = (const int*)d_in[28];
    const int*   tr       = (const int*)d_in[29];
    const int*   tp       = (const int*)d_in[30];

    const int N = in_sizes[0] / 3;     // nodes
    const int E = in_sizes[28] / 2;    // edges

    uint32_t *pcat_hi, *pcat_lo, *pe1_hi, *pe1_lo, *pe2_hi, *pe2_lo;
    uint32_t *pat_hi, *pat_lo, *ph_hi, *ph_lo, *pnt_hi, *pnt_lo, *pag_hi, *pag_lo, *wsplit;
    float *dlen;
    cudaGetSymbolAddress((void**)&pcat_hi, g_pcat_hi);
    cudaGetSymbolAddress((void**)&pcat_lo, g_pcat_lo);
    cudaGetSymbolAddress((void**)&pe1_hi,  g_pe1_hi);
    cudaGetSymbolAddress((void**)&pe1_lo,  g_pe1_lo);
    cudaGetSymbolAddress((void**)&pe2_hi,  g_pe2_hi);
    cudaGetSymbolAddress((void**)&pe2_lo,  g_pe2_lo);
    cudaGetSymbolAddress((void**)&pat_hi,  g_pat_hi);
    cudaGetSymbolAddress((void**)&pat_lo,  g_pat_lo);
    cudaGetSymbolAddress((void**)&ph_hi,   g_ph_hi);
    cudaGetSymbolAddress((void**)&ph_lo,   g_ph_lo);
    cudaGetSymbolAddress((void**)&pnt_hi,  g_pnt_hi);
    cudaGetSymbolAddress((void**)&pnt_lo,  g_pnt_lo);
    cudaGetSymbolAddress((void**)&pag_hi,  g_pag_hi);
    cudaGetSymbolAddress((void**)&pag_lo,  g_pag_lo);
    cudaGetSymbolAddress((void**)&wsplit,  g_wsplit);
    cudaGetSymbolAddress((void**)&dlen,    g_dlen);

    float* out = (float*)d_out;

    // ---- pre-split all GEMM weights in ONE launch (bf16 hi/lo, n-major) -----
    SplitArgs sa;
    const uint32_t* Wh[21]; const uint32_t* Wl[21];
    {
        size_t off = 0;
        int blk = 0;
        auto reg = [&](int idx, const float* W, int K, int Nc) {
            int P = K / 2;
            size_t S = (size_t)P * Nc;
            sa.W[idx]  = W;
            sa.hi[idx] = wsplit + off;
            sa.lo[idx] = wsplit + off + S;
            sa.P[idx]  = P;
            sa.Nc[idx] = Nc;
            sa.start[idx] = blk;
            Wh[idx] = sa.hi[idx]; Wl[idx] = sa.lo[idx];
            blk += (int)((S + 255) / 256);
            off += 2 * S;
        };
        reg(0, ee_W2, 256, 256);
        reg(1, ec_W1, 512, 256);
        reg(2, ec_W2, 256, 256);
        for (int l = 0; l < 4; l++) {
            reg(3 + l * 4 + 0, fW1  + (size_t)l * 65536, 256, 256);
            reg(3 + l * 4 + 1, fW2  + (size_t)l * 65536, 256, 256);
            reg(3 + l * 4 + 2, lin1 + (size_t)l * 65536, 256, 256);
            reg(3 + l * 4 + 3, lin2 + (size_t)l * 65536, 256, 256);
        }
        reg(19, g_W1, 512, 256);
        reg(20, g_W2, 256, 128);
        sa.start[21] = blk;
        k_splitW_all<<<blk, 256>>>(sa);
    }

    // 1) node embedding -> ph (packed)
    k_node_embed<<<N, 64>>>(r_feat, p_feat, emb_tab, feat_W, at, ph_hi, ph_lo);

    // 2) edge length + silu(d*W1+b1) -> pe1
    k_edge_d_h1<<<E, 128>>>(pos, ei, ee_W1, ee_b1, dlen, pe1_hi, pe1_lo, E);

    // 3) mlp_d GEMM with FUSED bond gating + concat -> pcat (512-wide)
    launch_gemm<0, false, true>(pe1_hi, pe1_lo, Wh[0], Wl[0], ee_b2,
                                pcat_hi, pcat_lo, E, 256, 256, bond_emb, tr, tp);

    // 5) edge_attr = silu(pcat @ ec_W1 + b1) @ ec_W2 + b2 -> pat
    gemm(pcat_hi, pcat_lo, Wh[1], Wl[1], ec_b1, pe1_hi, pe1_lo, E, 512, 256, 1, false);
    gemm(pe1_hi, pe1_lo, Wh[2], Wl[2], ec_b2, pat_hi, pat_lo, E, 256, 256, 0, false);

    // 6) 4 CFConv interaction blocks
    for (int l = 0; l < 4; l++) {
        const float* b1  = fb1  + (size_t)l * 256;
        const float* b2  = fb2  + (size_t)l * 256;
        const float* l2b = lin2b + (size_t)l * 256;
        int wi = 3 + l * 4;

        gemm(pat_hi, pat_lo, Wh[wi + 0], Wl[wi + 0], b1, pe1_hi, pe1_lo, E, 256, 256, 2, false);
        gemm(pe1_hi, pe1_lo, Wh[wi + 1], Wl[wi + 1], b2, pe2_hi, pe2_lo, E, 256, 256, 0, false);
        gemm(ph_hi, ph_lo, Wh[wi + 2], Wl[wi + 2], nullptr, pnt_hi, pnt_lo, N, 256, 256, 0, false);
        k_aggregate<<<N, 128>>>(pnt_hi, pnt_lo, pe2_hi, pe2_lo, pag_hi, pag_lo);
        gemm(pag_hi, pag_lo, Wh[wi + 3], Wl[wi + 3], l2b, ph_hi, ph_lo, N, 256, 256, 2, true);
    }

    // 7) pair features -> pcat
    k_pair<<<E, 256>>>(ph_hi, ph_lo, pat_hi, pat_lo, ei, pcat_hi, pcat_lo, E);

    // 8) output head
    gemm(pcat_hi, pcat_lo, Wh[19], Wl[19], g_b1, pe1_hi, pe1_lo, E, 512, 256, 1, false);
    gemm(pe1_hi, pe1_lo, Wh[20], Wl[20], g_b2, pe2_hi, pe2_lo, E, 256, 128, 1, false);
    k_final<<<(E + 7) / 8, 256>>>(pe2_hi, pe2_lo, g_W3, g_b3, out, E);

    // 9) remaining tuple outputs (edge_index, d) if compared
    if (out_size >= 4 * E) {
        k_extras<<<(2 * E + 255) / 256, 256>>>(ei, dlen, out, E);
    }
}